// round 11
// baseline (speedup 1.0000x reference)
#include <cuda_runtime.h>

#define PNUM    1024
#define BNUM    8
#define NB      11
#define NBINS   1331
#define IPB     4              // i-rows per block = 2 packed f32x2 units
#define THREADS 256
#define JSTEPS  (PNUM/THREADS) // 4
#define NBLOCKS (PNUM/IPB*BNUM) // 2048

typedef unsigned long long u64f2;   // two packed fp32

__device__ int g_hist[BNUM * NBINS];   // zero-init at load; last block resets
__device__ int g_done;                 // completion ticket; last block resets

// ---- packed f32x2 primitives (sm_100+) ----
__device__ __forceinline__ u64f2 pk2(float lo, float hi) {
    u64f2 r; asm("mov.b64 %0, {%1, %2};" : "=l"(r) : "f"(lo), "f"(hi)); return r;
}
__device__ __forceinline__ void up2(u64f2 v, float& lo, float& hi) {
    asm("mov.b64 {%0, %1}, %2;" : "=f"(lo), "=f"(hi) : "l"(v));
}
__device__ __forceinline__ u64f2 f2fma(u64f2 a, u64f2 b, u64f2 c) {
    u64f2 d; asm("fma.rn.f32x2 %0, %1, %2, %3;" : "=l"(d) : "l"(a), "l"(b), "l"(c)); return d;
}
__device__ __forceinline__ u64f2 f2mul(u64f2 a, u64f2 b) {
    u64f2 d; asm("mul.rn.f32x2 %0, %1, %2;" : "=l"(d) : "l"(a), "l"(b)); return d;
}
__device__ __forceinline__ u64f2 f2add(u64f2 a, u64f2 b) {
    u64f2 d; asm("add.rn.f32x2 %0, %1, %2;" : "=l"(d) : "l"(a), "l"(b)); return d;
}
__device__ __forceinline__ u64f2 f2sub(u64f2 a, u64f2 b) {
    u64f2 d; asm("sub.rn.f32x2 %0, %1, %2;" : "=l"(d) : "l"(a), "l"(b)); return d;
}
__device__ __forceinline__ u64f2 rsq2(u64f2 v) {   // per-lane rsqrt (MUFU is scalar)
    float a, b; up2(v, a, b);
    return pk2(rsqrtf(a), rsqrtf(b));
}
// packed cross component: a*b - c*d
__device__ __forceinline__ u64f2 f2cr(u64f2 a, u64f2 b, u64f2 c, u64f2 d) {
    return f2sub(f2mul(a, b), f2mul(c, d));
}

// Scalar tail: atan2 fixups + binning + histogram add (one pack lane).
__device__ __forceinline__ void epilogue(float af, float pf, float r, float y,
                                         bool aygt, bool xneg, int i, int j,
                                         int* __restrict__ hist) {
    if (aygt) r = 1.57079637f - r;
    if (xneg) r = 3.14159274f - r;
    float tf = fmaf(r, copysignf(1.75070429f, y), 5.5f);  // (r/pi)*5.5+5.5, sign of y
    int ai = min((int)af, NB - 1);
    int pb = min((int)pf, NB - 1);
    int ti = min((int)tf, NB - 1);
    int idx = (ai * NB + pb) * NB + ti;
    if (idx < 0) idx += NBINS;               // JAX: single negative wrap
    if ((unsigned)idx < (unsigned)NBINS && j != i)
        atomicAdd(&hist[idx], 1);
}

__global__ __launch_bounds__(THREADS, 4) void fpfh_fused_kernel(const float* __restrict__ x,
                                                                float* __restrict__ out) {
    __shared__ int s_hist[NBINS];
    __shared__ int s_last;

    const int b  = blockIdx.y;
    const int i0 = blockIdx.x * IPB;

    for (int t = threadIdx.x; t < NBINS; t += THREADS) s_hist[t] = 0;

    const float* __restrict__ base = x + (size_t)b * PNUM * 6;

    // i-point constants per unit u: lanes (i0+2u, i0+2u+1)
    u64f2 NPX[2], NPY[2], NPZ[2];      // -pos_i
    u64f2 NX[2],  NY[2],  NZ[2];       //  ni
    #pragma unroll
    for (int u = 0; u < 2; u++) {
        const float* p0 = base + (size_t)(i0 + 2 * u) * 6;
        const float* p1 = base + (size_t)(i0 + 2 * u + 1) * 6;
        NPX[u] = pk2(-__ldg(p0 + 0), -__ldg(p1 + 0));
        NPY[u] = pk2(-__ldg(p0 + 1), -__ldg(p1 + 1));
        NPZ[u] = pk2(-__ldg(p0 + 2), -__ldg(p1 + 2));
        NX[u]  = pk2( __ldg(p0 + 3),  __ldg(p1 + 3));
        NY[u]  = pk2( __ldg(p0 + 4),  __ldg(p1 + 4));
        NZ[u]  = pk2( __ldg(p0 + 5),  __ldg(p1 + 5));
    }
    __syncthreads();

    // packed atan polynomial constants (deg-11 minimax, err ~1e-6 rad)
    const u64f2 CA1  = pk2( 0.99997726f,  0.99997726f);
    const u64f2 CA3  = pk2(-0.33262347f, -0.33262347f);
    const u64f2 CA5  = pk2( 0.19354346f,  0.19354346f);
    const u64f2 CA7  = pk2(-0.11643287f, -0.11643287f);
    const u64f2 CA9  = pk2( 0.05265332f,  0.05265332f);
    const u64f2 CA11 = pk2(-0.01172120f, -0.01172120f);
    const u64f2 K55  = pk2( 5.5f, 5.5f);

    #pragma unroll 1
    for (int jj = 0; jj < JSTEPS; jj++) {
        const int j = threadIdx.x + jj * THREADS;
        const float2* __restrict__ pj = (const float2*)(base + (size_t)j * 6);
        const float2 q0 = __ldg(pj + 0);
        const float2 q1 = __ldg(pj + 1);
        const float2 q2 = __ldg(pj + 2);
        const u64f2 JX  = pk2(q0.x, q0.x), JY  = pk2(q0.y, q0.y), JZ  = pk2(q1.x, q1.x);
        const u64f2 JNX = pk2(q1.y, q1.y), JNY = pk2(q2.x, q2.x), JNZ = pk2(q2.y, q2.y);

        #pragma unroll
        for (int u = 0; u < 2; u++) {
            // delta = pos_j - pos_i
            const u64f2 dx = f2add(JX, NPX[u]);
            const u64f2 dy = f2add(JY, NPY[u]);
            const u64f2 dz = f2add(JZ, NPZ[u]);

            const u64f2 d2   = f2fma(dx, dx, f2fma(dy, dy, f2mul(dz, dz)));
            const u64f2 pdot = f2fma(NX[u], dx, f2fma(NY[u], dy, f2mul(NZ[u], dz)));
            const u64f2 phi2 = f2mul(pdot, rsq2(d2));

            // v = cross(delta, ni)
            const u64f2 vx = f2cr(dy, NZ[u], dz, NY[u]);
            const u64f2 vy = f2cr(dz, NX[u], dx, NZ[u]);
            const u64f2 vz = f2cr(dx, NY[u], dy, NX[u]);
            const u64f2 v2 = f2fma(vx, vx, f2fma(vy, vy, f2mul(vz, vz)));
            const u64f2 adot = f2fma(vx, JNX, f2fma(vy, JNY, f2mul(vz, JNZ)));
            const u64f2 alpha2 = f2mul(adot, rsq2(v2));

            // w = cross(ni, v)
            const u64f2 wx = f2cr(NY[u], vz, NZ[u], vy);
            const u64f2 wy = f2cr(NZ[u], vx, NX[u], vz);
            const u64f2 wz = f2cr(NX[u], vy, NY[u], vx);
            const u64f2 w2   = f2fma(wx, wx, f2fma(wy, wy, f2mul(wz, wz)));
            const u64f2 wdot = f2fma(wx, JNX, f2fma(wy, JNY, f2mul(wz, JNZ)));
            const u64f2 ndot = f2fma(NX[u], JNX, f2fma(NY[u], JNY, f2mul(NZ[u], JNZ)));

            // theta = atan2(wdot, ndot*|w|)  [scale-folded form]
            float w2a, w2b; up2(w2, w2a, w2b);
            float ya,  yb;  up2(wdot, ya, yb);
            float na,  nb;  up2(ndot, na, nb);
            const float xa = na * (w2a * rsqrtf(w2a));
            const float xb = nb * (w2b * rsqrtf(w2b));

            const float axa = fabsf(xa), aya = fabsf(ya);
            const float axb = fabsf(xb), ayb = fabsf(yb);
            const bool  ga = aya > axa, gb = ayb > axb;
            const bool  sa = xa < 0.0f, sb = xb < 0.0f;
            const float ta = __fdividef(fminf(axa, aya), fmaxf(axa, aya));
            const float tb = __fdividef(fminf(axb, ayb), fmaxf(axb, ayb));

            const u64f2 T  = pk2(ta, tb);
            const u64f2 T2 = f2mul(T, T);
            u64f2 P = f2fma(T2, CA11, CA9);
            P = f2fma(T2, P, CA7);
            P = f2fma(T2, P, CA5);
            P = f2fma(T2, P, CA3);
            P = f2fma(T2, P, CA1);
            const u64f2 R = f2mul(P, T);
            float ra, rb; up2(R, ra, rb);

            const u64f2 AF = f2fma(alpha2, K55, K55);
            const u64f2 PF = f2fma(phi2,  K55, K55);
            float afa, afb; up2(AF, afa, afb);
            float pfa, pfb; up2(PF, pfa, pfb);

            epilogue(afa, pfa, ra, ya, ga, sa, i0 + 2 * u,     j, s_hist);
            epilogue(afb, pfb, rb, yb, gb, sb, i0 + 2 * u + 1, j, s_hist);
        }
    }
    __syncthreads();

    // Flush block-private histogram to the per-batch global histogram.
    int* __restrict__ gh = &g_hist[b * NBINS];
    for (int t = threadIdx.x; t < NBINS; t += THREADS) {
        int c = s_hist[t];
        if (c) atomicAdd(&gh[t], c);
    }

    // Last-block-done finalize: one kernel, no extra launches.
    __threadfence();   // order g_hist RED ops before the ticket increment
    if (threadIdx.x == 0) {
        int prev = atomicAdd(&g_done, 1);
        s_last = (prev == NBLOCKS - 1);
    }
    __syncthreads();
    if (s_last) {
        __threadfence();   // acquire: see all blocks' g_hist updates
        for (int t = threadIdx.x; t < BNUM * NBINS; t += THREADS) {
            out[t] = (float)g_hist[t] / 1047552.0f;  // / (1024*1023)
            g_hist[t] = 0;                           // reset for next replay
        }
        __syncthreads();
        if (threadIdx.x == 0) g_done = 0;            // reset ticket
    }
}

extern "C" void kernel_launch(void* const* d_in, const int* in_sizes, int n_in,
                              void* d_out, int out_size) {
    const float* x = (const float*)d_in[0];
    float* out = (float*)d_out;

    dim3 grid(PNUM / IPB, BNUM);   // 256 x 8 = 2048 blocks
    fpfh_fused_kernel<<<grid, THREADS>>>(x, out);
}

// round 12
// speedup vs baseline: 1.2303x; 1.2303x over previous
#include <cuda_runtime.h>

#define PNUM    1024
#define BNUM    8
#define NB      11
#define NBINS   1331
#define IPB     4              // i-rows per block = 2 packed f32x2 units
#define THREADS 256
#define JSTEPS  (PNUM/THREADS) // 4
#define BPB     (PNUM/IPB)     // blocks per batch = 256

typedef unsigned long long u64f2;   // two packed fp32

__device__ int g_hist[BNUM * NBINS];   // zero-init at load; finalizers reset
__device__ int g_done[BNUM];           // per-batch completion tickets

// ---- packed f32x2 primitives (sm_100+) ----
__device__ __forceinline__ u64f2 pk2(float lo, float hi) {
    u64f2 r; asm("mov.b64 %0, {%1, %2};" : "=l"(r) : "f"(lo), "f"(hi)); return r;
}
__device__ __forceinline__ void up2(u64f2 v, float& lo, float& hi) {
    asm("mov.b64 {%0, %1}, %2;" : "=f"(lo), "=f"(hi) : "l"(v));
}
__device__ __forceinline__ u64f2 f2fma(u64f2 a, u64f2 b, u64f2 c) {
    u64f2 d; asm("fma.rn.f32x2 %0, %1, %2, %3;" : "=l"(d) : "l"(a), "l"(b), "l"(c)); return d;
}
__device__ __forceinline__ u64f2 f2mul(u64f2 a, u64f2 b) {
    u64f2 d; asm("mul.rn.f32x2 %0, %1, %2;" : "=l"(d) : "l"(a), "l"(b)); return d;
}
__device__ __forceinline__ u64f2 f2add(u64f2 a, u64f2 b) {
    u64f2 d; asm("add.rn.f32x2 %0, %1, %2;" : "=l"(d) : "l"(a), "l"(b)); return d;
}
__device__ __forceinline__ u64f2 f2sub(u64f2 a, u64f2 b) {
    u64f2 d; asm("sub.rn.f32x2 %0, %1, %2;" : "=l"(d) : "l"(a), "l"(b)); return d;
}
__device__ __forceinline__ u64f2 rsq2(u64f2 v) {   // per-lane rsqrt (MUFU is scalar)
    float a, b; up2(v, a, b);
    return pk2(rsqrtf(a), rsqrtf(b));
}
// packed cross component: a*b - c*d
__device__ __forceinline__ u64f2 f2cr(u64f2 a, u64f2 b, u64f2 c, u64f2 d) {
    return f2sub(f2mul(a, b), f2mul(c, d));
}

// Scalar tail: atan2 fixups + binning + histogram add (one pack lane).
__device__ __forceinline__ void epilogue(float af, float pf, float r, float y,
                                         bool aygt, bool xneg, int i, int j,
                                         int* __restrict__ hist) {
    if (aygt) r = 1.57079637f - r;
    if (xneg) r = 3.14159274f - r;
    float tf = fmaf(r, copysignf(1.75070429f, y), 5.5f);  // (r/pi)*5.5+5.5, sign of y
    int ai = min((int)af, NB - 1);
    int pb = min((int)pf, NB - 1);
    int ti = min((int)tf, NB - 1);
    int idx = (ai * NB + pb) * NB + ti;
    if (idx < 0) idx += NBINS;               // JAX: single negative wrap
    if ((unsigned)idx < (unsigned)NBINS && j != i)
        atomicAdd(&hist[idx], 1);
}

__global__ __launch_bounds__(THREADS, 4) void fpfh_fused_kernel(const float* __restrict__ x,
                                                                float* __restrict__ out) {
    __shared__ int s_hist[NBINS];
    __shared__ int s_last;

    const int b  = blockIdx.y;
    const int i0 = blockIdx.x * IPB;

    for (int t = threadIdx.x; t < NBINS; t += THREADS) s_hist[t] = 0;

    const float* __restrict__ base = x + (size_t)b * PNUM * 6;

    // i-point constants per unit u: lanes (i0+2u, i0+2u+1)
    u64f2 NPX[2], NPY[2], NPZ[2];      // -pos_i
    u64f2 NX[2],  NY[2],  NZ[2];       //  ni
    #pragma unroll
    for (int u = 0; u < 2; u++) {
        const float* p0 = base + (size_t)(i0 + 2 * u) * 6;
        const float* p1 = base + (size_t)(i0 + 2 * u + 1) * 6;
        NPX[u] = pk2(-__ldg(p0 + 0), -__ldg(p1 + 0));
        NPY[u] = pk2(-__ldg(p0 + 1), -__ldg(p1 + 1));
        NPZ[u] = pk2(-__ldg(p0 + 2), -__ldg(p1 + 2));
        NX[u]  = pk2( __ldg(p0 + 3),  __ldg(p1 + 3));
        NY[u]  = pk2( __ldg(p0 + 4),  __ldg(p1 + 4));
        NZ[u]  = pk2( __ldg(p0 + 5),  __ldg(p1 + 5));
    }
    __syncthreads();

    // packed atan polynomial constants (deg-11 minimax, err ~1e-6 rad)
    const u64f2 CA1  = pk2( 0.99997726f,  0.99997726f);
    const u64f2 CA3  = pk2(-0.33262347f, -0.33262347f);
    const u64f2 CA5  = pk2( 0.19354346f,  0.19354346f);
    const u64f2 CA7  = pk2(-0.11643287f, -0.11643287f);
    const u64f2 CA9  = pk2( 0.05265332f,  0.05265332f);
    const u64f2 CA11 = pk2(-0.01172120f, -0.01172120f);
    const u64f2 K55  = pk2( 5.5f, 5.5f);

    #pragma unroll 1
    for (int jj = 0; jj < JSTEPS; jj++) {
        const int j = threadIdx.x + jj * THREADS;
        const float2* __restrict__ pj = (const float2*)(base + (size_t)j * 6);
        const float2 q0 = __ldg(pj + 0);
        const float2 q1 = __ldg(pj + 1);
        const float2 q2 = __ldg(pj + 2);
        const u64f2 JX  = pk2(q0.x, q0.x), JY  = pk2(q0.y, q0.y), JZ  = pk2(q1.x, q1.x);
        const u64f2 JNX = pk2(q1.y, q1.y), JNY = pk2(q2.x, q2.x), JNZ = pk2(q2.y, q2.y);

        #pragma unroll
        for (int u = 0; u < 2; u++) {
            // delta = pos_j - pos_i
            const u64f2 dx = f2add(JX, NPX[u]);
            const u64f2 dy = f2add(JY, NPY[u]);
            const u64f2 dz = f2add(JZ, NPZ[u]);

            const u64f2 d2   = f2fma(dx, dx, f2fma(dy, dy, f2mul(dz, dz)));
            const u64f2 pdot = f2fma(NX[u], dx, f2fma(NY[u], dy, f2mul(NZ[u], dz)));
            const u64f2 phi2 = f2mul(pdot, rsq2(d2));

            // v = cross(delta, ni)
            const u64f2 vx = f2cr(dy, NZ[u], dz, NY[u]);
            const u64f2 vy = f2cr(dz, NX[u], dx, NZ[u]);
            const u64f2 vz = f2cr(dx, NY[u], dy, NX[u]);
            const u64f2 v2 = f2fma(vx, vx, f2fma(vy, vy, f2mul(vz, vz)));
            const u64f2 adot = f2fma(vx, JNX, f2fma(vy, JNY, f2mul(vz, JNZ)));
            const u64f2 alpha2 = f2mul(adot, rsq2(v2));

            // w = cross(ni, v)
            const u64f2 wx = f2cr(NY[u], vz, NZ[u], vy);
            const u64f2 wy = f2cr(NZ[u], vx, NX[u], vz);
            const u64f2 wz = f2cr(NX[u], vy, NY[u], vx);
            const u64f2 w2   = f2fma(wx, wx, f2fma(wy, wy, f2mul(wz, wz)));
            const u64f2 wdot = f2fma(wx, JNX, f2fma(wy, JNY, f2mul(wz, JNZ)));
            const u64f2 ndot = f2fma(NX[u], JNX, f2fma(NY[u], JNY, f2mul(NZ[u], JNZ)));

            // theta = atan2(wdot, ndot*|w|)  [scale-folded form]
            float w2a, w2b; up2(w2, w2a, w2b);
            float ya,  yb;  up2(wdot, ya, yb);
            float na,  nb;  up2(ndot, na, nb);
            const float xa = na * (w2a * rsqrtf(w2a));
            const float xb = nb * (w2b * rsqrtf(w2b));

            const float axa = fabsf(xa), aya = fabsf(ya);
            const float axb = fabsf(xb), ayb = fabsf(yb);
            const bool  ga = aya > axa, gb = ayb > axb;
            const bool  sa = xa < 0.0f, sb = xb < 0.0f;
            const float ta = __fdividef(fminf(axa, aya), fmaxf(axa, aya));
            const float tb = __fdividef(fminf(axb, ayb), fmaxf(axb, ayb));

            const u64f2 T  = pk2(ta, tb);
            const u64f2 T2 = f2mul(T, T);
            u64f2 P = f2fma(T2, CA11, CA9);
            P = f2fma(T2, P, CA7);
            P = f2fma(T2, P, CA5);
            P = f2fma(T2, P, CA3);
            P = f2fma(T2, P, CA1);
            const u64f2 R = f2mul(P, T);
            float ra, rb; up2(R, ra, rb);

            const u64f2 AF = f2fma(alpha2, K55, K55);
            const u64f2 PF = f2fma(phi2,  K55, K55);
            float afa, afb; up2(AF, afa, afb);
            float pfa, pfb; up2(PF, pfa, pfb);

            epilogue(afa, pfa, ra, ya, ga, sa, i0 + 2 * u,     j, s_hist);
            epilogue(afb, pfb, rb, yb, gb, sb, i0 + 2 * u + 1, j, s_hist);
        }
    }
    __syncthreads();

    // Flush block-private histogram to the per-batch global histogram.
    int* __restrict__ gh = &g_hist[b * NBINS];
    for (int t = threadIdx.x; t < NBINS; t += THREADS) {
        int c = s_hist[t];
        if (c) atomicAdd(&gh[t], c);
    }

    // Per-batch last-block finalize: 8 finalizer blocks run in parallel,
    // each handling only its batch's 1331 bins (~5 iters/thread).
    __threadfence();   // order this block's g_hist REDs before its ticket bump
    if (threadIdx.x == 0) {
        int prev = atomicAdd(&g_done[b], 1);
        s_last = (prev == BPB - 1);
    }
    __syncthreads();
    if (s_last) {
        __threadfence();   // acquire: see all of this batch's g_hist updates
        float* __restrict__ ob = out + b * NBINS;
        for (int t = threadIdx.x; t < NBINS; t += THREADS) {
            ob[t] = (float)gh[t] / 1047552.0f;   // / (1024*1023)
            gh[t] = 0;                           // reset for next replay
        }
        __syncthreads();
        if (threadIdx.x == 0) g_done[b] = 0;     // reset ticket
    }
}

extern "C" void kernel_launch(void* const* d_in, const int* in_sizes, int n_in,
                              void* d_out, int out_size) {
    const float* x = (const float*)d_in[0];
    float* out = (float*)d_out;

    dim3 grid(BPB, BNUM);   // 256 x 8 = 2048 blocks
    fpfh_fused_kernel<<<grid, THREADS>>>(x, out);
}

// round 13
// speedup vs baseline: 1.4472x; 1.1763x over previous
#include <cuda_runtime.h>

#define PNUM    1024
#define BNUM    8
#define NB      11
#define NBINS   1331
#define IPB     4              // i-rows per block = 2 packed f32x2 units
#define THREADS 256
#define JSTEPS  (PNUM/THREADS) // 4
#define BPB     (PNUM/IPB)     // 256 blocks per batch

typedef unsigned long long u64f2;   // two packed fp32

// ---- packed f32x2 primitives (sm_100+) ----
__device__ __forceinline__ u64f2 pk2(float lo, float hi) {
    u64f2 r; asm("mov.b64 %0, {%1, %2};" : "=l"(r) : "f"(lo), "f"(hi)); return r;
}
__device__ __forceinline__ void up2(u64f2 v, float& lo, float& hi) {
    asm("mov.b64 {%0, %1}, %2;" : "=f"(lo), "=f"(hi) : "l"(v));
}
__device__ __forceinline__ u64f2 f2fma(u64f2 a, u64f2 b, u64f2 c) {
    u64f2 d; asm("fma.rn.f32x2 %0, %1, %2, %3;" : "=l"(d) : "l"(a), "l"(b), "l"(c)); return d;
}
__device__ __forceinline__ u64f2 f2mul(u64f2 a, u64f2 b) {
    u64f2 d; asm("mul.rn.f32x2 %0, %1, %2;" : "=l"(d) : "l"(a), "l"(b)); return d;
}
__device__ __forceinline__ u64f2 f2add(u64f2 a, u64f2 b) {
    u64f2 d; asm("add.rn.f32x2 %0, %1, %2;" : "=l"(d) : "l"(a), "l"(b)); return d;
}
__device__ __forceinline__ u64f2 f2sub(u64f2 a, u64f2 b) {
    u64f2 d; asm("sub.rn.f32x2 %0, %1, %2;" : "=l"(d) : "l"(a), "l"(b)); return d;
}
__device__ __forceinline__ u64f2 rsq2(u64f2 v) {   // per-lane rsqrt (MUFU is scalar)
    float a, b; up2(v, a, b);
    return pk2(rsqrtf(a), rsqrtf(b));
}
// packed cross component: a*b - c*d
__device__ __forceinline__ u64f2 f2cr(u64f2 a, u64f2 b, u64f2 c, u64f2 d) {
    return f2sub(f2mul(a, b), f2mul(c, d));
}

// Scalar tail: atan2 fixups + binning + histogram add (one pack lane).
__device__ __forceinline__ void epilogue(float af, float pf, float r, float y,
                                         bool aygt, bool xneg, int i, int j,
                                         int* __restrict__ hist) {
    if (aygt) r = 1.57079637f - r;
    if (xneg) r = 3.14159274f - r;
    float tf = fmaf(r, copysignf(1.75070429f, y), 5.5f);  // (r/pi)*5.5+5.5, sign of y
    int ai = min((int)af, NB - 1);
    int pb = min((int)pf, NB - 1);
    int ti = min((int)tf, NB - 1);
    int idx = (ai * NB + pb) * NB + ti;
    if (idx < 0) idx += NBINS;               // JAX: single negative wrap
    if ((unsigned)idx < (unsigned)NBINS && j != i)
        atomicAdd(&hist[idx], 1);
}

// Launch 1: zero the output (it is poisoned 0xAA before timing).
__global__ void fpfh_zero_out_kernel(float* __restrict__ out) {
    int t = blockIdx.x * blockDim.x + threadIdx.x;
    if (t < BNUM * NBINS) out[t] = 0.0f;
}

// Launch 2: accumulate; flush block-private histogram straight into out.
__global__ __launch_bounds__(THREADS, 3) void fpfh_accum_kernel(const float* __restrict__ x,
                                                                float* __restrict__ out) {
    __shared__ int s_hist[NBINS];

    const int b  = blockIdx.y;
    const int i0 = blockIdx.x * IPB;

    for (int t = threadIdx.x; t < NBINS; t += THREADS) s_hist[t] = 0;

    const float* __restrict__ base = x + (size_t)b * PNUM * 6;

    // i-point constants per unit u: lanes (i0+2u, i0+2u+1)
    u64f2 NPX[2], NPY[2], NPZ[2];      // -pos_i
    u64f2 NX[2],  NY[2],  NZ[2];       //  ni
    #pragma unroll
    for (int u = 0; u < 2; u++) {
        const float* p0 = base + (size_t)(i0 + 2 * u) * 6;
        const float* p1 = base + (size_t)(i0 + 2 * u + 1) * 6;
        NPX[u] = pk2(-__ldg(p0 + 0), -__ldg(p1 + 0));
        NPY[u] = pk2(-__ldg(p0 + 1), -__ldg(p1 + 1));
        NPZ[u] = pk2(-__ldg(p0 + 2), -__ldg(p1 + 2));
        NX[u]  = pk2( __ldg(p0 + 3),  __ldg(p1 + 3));
        NY[u]  = pk2( __ldg(p0 + 4),  __ldg(p1 + 4));
        NZ[u]  = pk2( __ldg(p0 + 5),  __ldg(p1 + 5));
    }
    __syncthreads();

    // packed atan polynomial constants (deg-11 minimax, err ~1e-6 rad)
    const u64f2 CA1  = pk2( 0.99997726f,  0.99997726f);
    const u64f2 CA3  = pk2(-0.33262347f, -0.33262347f);
    const u64f2 CA5  = pk2( 0.19354346f,  0.19354346f);
    const u64f2 CA7  = pk2(-0.11643287f, -0.11643287f);
    const u64f2 CA9  = pk2( 0.05265332f,  0.05265332f);
    const u64f2 CA11 = pk2(-0.01172120f, -0.01172120f);
    const u64f2 K55  = pk2( 5.5f, 5.5f);

    #pragma unroll 2
    for (int jj = 0; jj < JSTEPS; jj++) {
        const int j = threadIdx.x + jj * THREADS;
        const float2* __restrict__ pj = (const float2*)(base + (size_t)j * 6);
        const float2 q0 = __ldg(pj + 0);
        const float2 q1 = __ldg(pj + 1);
        const float2 q2 = __ldg(pj + 2);
        const u64f2 JX  = pk2(q0.x, q0.x), JY  = pk2(q0.y, q0.y), JZ  = pk2(q1.x, q1.x);
        const u64f2 JNX = pk2(q1.y, q1.y), JNY = pk2(q2.x, q2.x), JNZ = pk2(q2.y, q2.y);

        #pragma unroll
        for (int u = 0; u < 2; u++) {
            // delta = pos_j - pos_i
            const u64f2 dx = f2add(JX, NPX[u]);
            const u64f2 dy = f2add(JY, NPY[u]);
            const u64f2 dz = f2add(JZ, NPZ[u]);

            const u64f2 d2   = f2fma(dx, dx, f2fma(dy, dy, f2mul(dz, dz)));
            const u64f2 pdot = f2fma(NX[u], dx, f2fma(NY[u], dy, f2mul(NZ[u], dz)));
            const u64f2 phi2 = f2mul(pdot, rsq2(d2));

            // v = cross(delta, ni)
            const u64f2 vx = f2cr(dy, NZ[u], dz, NY[u]);
            const u64f2 vy = f2cr(dz, NX[u], dx, NZ[u]);
            const u64f2 vz = f2cr(dx, NY[u], dy, NX[u]);
            const u64f2 v2 = f2fma(vx, vx, f2fma(vy, vy, f2mul(vz, vz)));
            const u64f2 adot = f2fma(vx, JNX, f2fma(vy, JNY, f2mul(vz, JNZ)));
            const u64f2 alpha2 = f2mul(adot, rsq2(v2));

            // w = cross(ni, v)
            const u64f2 wx = f2cr(NY[u], vz, NZ[u], vy);
            const u64f2 wy = f2cr(NZ[u], vx, NX[u], vz);
            const u64f2 wz = f2cr(NX[u], vy, NY[u], vx);
            const u64f2 w2   = f2fma(wx, wx, f2fma(wy, wy, f2mul(wz, wz)));
            const u64f2 wdot = f2fma(wx, JNX, f2fma(wy, JNY, f2mul(wz, JNZ)));
            const u64f2 ndot = f2fma(NX[u], JNX, f2fma(NY[u], JNY, f2mul(NZ[u], JNZ)));

            // theta = atan2(wdot, ndot*|w|)  [scale-folded form]
            float w2a, w2b; up2(w2, w2a, w2b);
            float ya,  yb;  up2(wdot, ya, yb);
            float na,  nb;  up2(ndot, na, nb);
            const float xa = na * (w2a * rsqrtf(w2a));
            const float xb = nb * (w2b * rsqrtf(w2b));

            const float axa = fabsf(xa), aya = fabsf(ya);
            const float axb = fabsf(xb), ayb = fabsf(yb);
            const bool  ga = aya > axa, gb = ayb > axb;
            const bool  sa = xa < 0.0f, sb = xb < 0.0f;
            const float ta = __fdividef(fminf(axa, aya), fmaxf(axa, aya));
            const float tb = __fdividef(fminf(axb, ayb), fmaxf(axb, ayb));

            const u64f2 T  = pk2(ta, tb);
            const u64f2 T2 = f2mul(T, T);
            u64f2 P = f2fma(T2, CA11, CA9);
            P = f2fma(T2, P, CA7);
            P = f2fma(T2, P, CA5);
            P = f2fma(T2, P, CA3);
            P = f2fma(T2, P, CA1);
            const u64f2 R = f2mul(P, T);
            float ra, rb; up2(R, ra, rb);

            const u64f2 AF = f2fma(alpha2, K55, K55);
            const u64f2 PF = f2fma(phi2,  K55, K55);
            float afa, afb; up2(AF, afa, afb);
            float pfa, pfb; up2(PF, pfa, pfb);

            epilogue(afa, pfa, ra, ya, ga, sa, i0 + 2 * u,     j, s_hist);
            epilogue(afb, pfb, rb, yb, gb, sb, i0 + 2 * u + 1, j, s_hist);
        }
    }
    __syncthreads();

    // Flush directly into out: c / (1024*1023) as scaled float RED.
    const float kInv = 1.0f / 1047552.0f;
    float* __restrict__ ob = out + b * NBINS;
    for (int t = threadIdx.x; t < NBINS; t += THREADS) {
        int c = s_hist[t];
        if (c) atomicAdd(&ob[t], (float)c * kInv);
    }
}

extern "C" void kernel_launch(void* const* d_in, const int* in_sizes, int n_in,
                              void* d_out, int out_size) {
    const float* x = (const float*)d_in[0];
    float* out = (float*)d_out;

    int total = BNUM * NBINS;
    fpfh_zero_out_kernel<<<(total + 255) / 256, 256>>>(out);

    dim3 grid(BPB, BNUM);   // 256 x 8 = 2048 blocks
    fpfh_accum_kernel<<<grid, THREADS>>>(x, out);
}

// round 14
// speedup vs baseline: 1.4539x; 1.0046x over previous
#include <cuda_runtime.h>

#define PNUM    1024
#define BNUM    8
#define NB      11
#define NBINS   1331
#define IPB     4              // i-rows per block = 2 packed f32x2 units
#define THREADS 256
#define JSTEPS  (PNUM/THREADS) // 4
#define BPB     (PNUM/IPB)     // 256 blocks per batch

typedef unsigned long long u64f2;   // two packed fp32

// ---- packed f32x2 primitives (sm_100+) ----
__device__ __forceinline__ u64f2 pk2(float lo, float hi) {
    u64f2 r; asm("mov.b64 %0, {%1, %2};" : "=l"(r) : "f"(lo), "f"(hi)); return r;
}
__device__ __forceinline__ void up2(u64f2 v, float& lo, float& hi) {
    asm("mov.b64 {%0, %1}, %2;" : "=f"(lo), "=f"(hi) : "l"(v));
}
__device__ __forceinline__ u64f2 f2fma(u64f2 a, u64f2 b, u64f2 c) {
    u64f2 d; asm("fma.rn.f32x2 %0, %1, %2, %3;" : "=l"(d) : "l"(a), "l"(b), "l"(c)); return d;
}
__device__ __forceinline__ u64f2 f2mul(u64f2 a, u64f2 b) {
    u64f2 d; asm("mul.rn.f32x2 %0, %1, %2;" : "=l"(d) : "l"(a), "l"(b)); return d;
}
__device__ __forceinline__ u64f2 f2add(u64f2 a, u64f2 b) {
    u64f2 d; asm("add.rn.f32x2 %0, %1, %2;" : "=l"(d) : "l"(a), "l"(b)); return d;
}
__device__ __forceinline__ u64f2 f2sub(u64f2 a, u64f2 b) {
    u64f2 d; asm("sub.rn.f32x2 %0, %1, %2;" : "=l"(d) : "l"(a), "l"(b)); return d;
}
__device__ __forceinline__ u64f2 rsq2(u64f2 v) {   // per-lane rsqrt (MUFU is scalar)
    float a, b; up2(v, a, b);
    return pk2(rsqrtf(a), rsqrtf(b));
}
// packed cross component: a*b - c*d
__device__ __forceinline__ u64f2 f2cr(u64f2 a, u64f2 b, u64f2 c, u64f2 d) {
    return f2sub(f2mul(a, b), f2mul(c, d));
}

// Scalar tail: atan2 fixups + binning + histogram add (one pack lane).
__device__ __forceinline__ void epilogue(float af, float pf, float r, float y,
                                         bool aygt, bool xneg, int i, int j,
                                         int* __restrict__ hist) {
    if (aygt) r = 1.57079637f - r;
    if (xneg) r = 3.14159274f - r;
    float tf = fmaf(r, copysignf(1.75070429f, y), 5.5f);  // (r/pi)*5.5+5.5, sign of y
    int ai = min((int)af, NB - 1);
    int pb = min((int)pf, NB - 1);
    int ti = min((int)tf, NB - 1);
    int idx = (ai * NB + pb) * NB + ti;
    if (idx < 0) idx += NBINS;               // JAX: single negative wrap
    if ((unsigned)idx < (unsigned)NBINS && j != i)
        atomicAdd(&hist[idx], 1);
}

// Launch 1: zero the output (it is poisoned 0xAA before timing).
__global__ void fpfh_zero_out_kernel(float* __restrict__ out) {
    int t = blockIdx.x * blockDim.x + threadIdx.x;
    if (t < BNUM * NBINS) out[t] = 0.0f;
}

// Launch 2: accumulate; flush block-private histogram straight into out.
__global__ __launch_bounds__(THREADS, 4) void fpfh_accum_kernel(const float* __restrict__ x,
                                                                float* __restrict__ out) {
    __shared__ int s_hist[NBINS];

    const int b  = blockIdx.y;
    const int i0 = blockIdx.x * IPB;

    for (int t = threadIdx.x; t < NBINS; t += THREADS) s_hist[t] = 0;

    const float* __restrict__ base = x + (size_t)b * PNUM * 6;

    // i-point constants per unit u: lanes (i0+2u, i0+2u+1)
    u64f2 NPX[2], NPY[2], NPZ[2];      // -pos_i
    u64f2 NX[2],  NY[2],  NZ[2];       //  ni
    #pragma unroll
    for (int u = 0; u < 2; u++) {
        const float* p0 = base + (size_t)(i0 + 2 * u) * 6;
        const float* p1 = base + (size_t)(i0 + 2 * u + 1) * 6;
        NPX[u] = pk2(-__ldg(p0 + 0), -__ldg(p1 + 0));
        NPY[u] = pk2(-__ldg(p0 + 1), -__ldg(p1 + 1));
        NPZ[u] = pk2(-__ldg(p0 + 2), -__ldg(p1 + 2));
        NX[u]  = pk2( __ldg(p0 + 3),  __ldg(p1 + 3));
        NY[u]  = pk2( __ldg(p0 + 4),  __ldg(p1 + 4));
        NZ[u]  = pk2( __ldg(p0 + 5),  __ldg(p1 + 5));
    }
    __syncthreads();

    // packed atan polynomial constants (deg-11 minimax, err ~1e-6 rad)
    const u64f2 CA1  = pk2( 0.99997726f,  0.99997726f);
    const u64f2 CA3  = pk2(-0.33262347f, -0.33262347f);
    const u64f2 CA5  = pk2( 0.19354346f,  0.19354346f);
    const u64f2 CA7  = pk2(-0.11643287f, -0.11643287f);
    const u64f2 CA9  = pk2( 0.05265332f,  0.05265332f);
    const u64f2 CA11 = pk2(-0.01172120f, -0.01172120f);
    const u64f2 K55  = pk2( 5.5f, 5.5f);

    #pragma unroll 1
    for (int jj = 0; jj < JSTEPS; jj++) {
        const int j = threadIdx.x + jj * THREADS;
        const float2* __restrict__ pj = (const float2*)(base + (size_t)j * 6);
        const float2 q0 = __ldg(pj + 0);
        const float2 q1 = __ldg(pj + 1);
        const float2 q2 = __ldg(pj + 2);
        const u64f2 JX  = pk2(q0.x, q0.x), JY  = pk2(q0.y, q0.y), JZ  = pk2(q1.x, q1.x);
        const u64f2 JNX = pk2(q1.y, q1.y), JNY = pk2(q2.x, q2.x), JNZ = pk2(q2.y, q2.y);

        #pragma unroll
        for (int u = 0; u < 2; u++) {
            // delta = pos_j - pos_i
            const u64f2 dx = f2add(JX, NPX[u]);
            const u64f2 dy = f2add(JY, NPY[u]);
            const u64f2 dz = f2add(JZ, NPZ[u]);

            const u64f2 d2   = f2fma(dx, dx, f2fma(dy, dy, f2mul(dz, dz)));
            const u64f2 pdot = f2fma(NX[u], dx, f2fma(NY[u], dy, f2mul(NZ[u], dz)));
            const u64f2 phi2 = f2mul(pdot, rsq2(d2));

            // v = cross(delta, ni)
            const u64f2 vx = f2cr(dy, NZ[u], dz, NY[u]);
            const u64f2 vy = f2cr(dz, NX[u], dx, NZ[u]);
            const u64f2 vz = f2cr(dx, NY[u], dy, NX[u]);
            const u64f2 v2 = f2fma(vx, vx, f2fma(vy, vy, f2mul(vz, vz)));
            const u64f2 adot = f2fma(vx, JNX, f2fma(vy, JNY, f2mul(vz, JNZ)));
            const u64f2 alpha2 = f2mul(adot, rsq2(v2));

            // w = cross(ni, v)
            const u64f2 wx = f2cr(NY[u], vz, NZ[u], vy);
            const u64f2 wy = f2cr(NZ[u], vx, NX[u], vz);
            const u64f2 wz = f2cr(NX[u], vy, NY[u], vx);
            const u64f2 w2   = f2fma(wx, wx, f2fma(wy, wy, f2mul(wz, wz)));
            const u64f2 wdot = f2fma(wx, JNX, f2fma(wy, JNY, f2mul(wz, JNZ)));
            const u64f2 ndot = f2fma(NX[u], JNX, f2fma(NY[u], JNY, f2mul(NZ[u], JNZ)));

            // theta = atan2(wdot, ndot*|w|)  [scale-folded form]
            float w2a, w2b; up2(w2, w2a, w2b);
            float ya,  yb;  up2(wdot, ya, yb);
            float na,  nb;  up2(ndot, na, nb);
            const float xa = na * (w2a * rsqrtf(w2a));
            const float xb = nb * (w2b * rsqrtf(w2b));

            const float axa = fabsf(xa), aya = fabsf(ya);
            const float axb = fabsf(xb), ayb = fabsf(yb);
            const bool  ga = aya > axa, gb = ayb > axb;
            const bool  sa = xa < 0.0f, sb = xb < 0.0f;
            const float ta = __fdividef(fminf(axa, aya), fmaxf(axa, aya));
            const float tb = __fdividef(fminf(axb, ayb), fmaxf(axb, ayb));

            const u64f2 T  = pk2(ta, tb);
            const u64f2 T2 = f2mul(T, T);
            u64f2 P = f2fma(T2, CA11, CA9);
            P = f2fma(T2, P, CA7);
            P = f2fma(T2, P, CA5);
            P = f2fma(T2, P, CA3);
            P = f2fma(T2, P, CA1);
            const u64f2 R = f2mul(P, T);
            float ra, rb; up2(R, ra, rb);

            const u64f2 AF = f2fma(alpha2, K55, K55);
            const u64f2 PF = f2fma(phi2,  K55, K55);
            float afa, afb; up2(AF, afa, afb);
            float pfa, pfb; up2(PF, pfa, pfb);

            epilogue(afa, pfa, ra, ya, ga, sa, i0 + 2 * u,     j, s_hist);
            epilogue(afb, pfb, rb, yb, gb, sb, i0 + 2 * u + 1, j, s_hist);
        }
    }
    __syncthreads();

    // Flush directly into out: c / (1024*1023) as scaled float RED.
    const float kInv = 1.0f / 1047552.0f;
    float* __restrict__ ob = out + b * NBINS;
    for (int t = threadIdx.x; t < NBINS; t += THREADS) {
        int c = s_hist[t];
        if (c) atomicAdd(&ob[t], (float)c * kInv);
    }
}

extern "C" void kernel_launch(void* const* d_in, const int* in_sizes, int n_in,
                              void* d_out, int out_size) {
    const float* x = (const float*)d_in[0];
    float* out = (float*)d_out;

    int total = BNUM * NBINS;
    fpfh_zero_out_kernel<<<(total + 255) / 256, 256>>>(out);

    dim3 grid(BPB, BNUM);   // 256 x 8 = 2048 blocks
    fpfh_accum_kernel<<<grid, THREADS>>>(x, out);
}

// round 15
// speedup vs baseline: 1.5316x; 1.0534x over previous
#include <cuda_runtime.h>

#define PNUM    1024
#define BNUM    8
#define NB      11
#define NBINS   1331
#define IPB     4              // i-rows per block = 2 packed f32x2 units
#define THREADS 256
#define JSTEPS  (PNUM/THREADS) // 4
#define BPB     (PNUM/IPB)     // 256 blocks per batch

typedef unsigned long long u64f2;   // two packed fp32

// ---- packed f32x2 primitives (sm_100+) ----
__device__ __forceinline__ u64f2 pk2(float lo, float hi) {
    u64f2 r; asm("mov.b64 %0, {%1, %2};" : "=l"(r) : "f"(lo), "f"(hi)); return r;
}
__device__ __forceinline__ void up2(u64f2 v, float& lo, float& hi) {
    asm("mov.b64 {%0, %1}, %2;" : "=f"(lo), "=f"(hi) : "l"(v));
}
__device__ __forceinline__ u64f2 f2fma(u64f2 a, u64f2 b, u64f2 c) {
    u64f2 d; asm("fma.rn.f32x2 %0, %1, %2, %3;" : "=l"(d) : "l"(a), "l"(b), "l"(c)); return d;
}
__device__ __forceinline__ u64f2 f2mul(u64f2 a, u64f2 b) {
    u64f2 d; asm("mul.rn.f32x2 %0, %1, %2;" : "=l"(d) : "l"(a), "l"(b)); return d;
}
__device__ __forceinline__ u64f2 f2add(u64f2 a, u64f2 b) {
    u64f2 d; asm("add.rn.f32x2 %0, %1, %2;" : "=l"(d) : "l"(a), "l"(b)); return d;
}
__device__ __forceinline__ u64f2 f2sub(u64f2 a, u64f2 b) {
    u64f2 d; asm("sub.rn.f32x2 %0, %1, %2;" : "=l"(d) : "l"(a), "l"(b)); return d;
}
__device__ __forceinline__ u64f2 rsq2(u64f2 v) {   // per-lane rsqrt (MUFU is scalar)
    float a, b; up2(v, a, b);
    return pk2(rsqrtf(a), rsqrtf(b));
}
// packed cross component: a*b - c*d
__device__ __forceinline__ u64f2 f2cr(u64f2 a, u64f2 b, u64f2 c, u64f2 d) {
    return f2sub(f2mul(a, b), f2mul(c, d));
}

// theta sector count for one lane: A = ndot^2*w2, B = wdot^2, km = K_m*B.
__device__ __forceinline__ int theta_bin(float A, float nd, float y,
                                         float k1, float k2, float k3,
                                         float k4, float k5) {
    int cpos = (int)(A <= k1) + (int)(A <= k2) + (int)(A <= k3);
    int cneg = 3 + (int)(A >= k4) + (int)(A >= k5);
    int c = (nd < 0.0f) ? cneg : cpos;
    return (y >= 0.0f) ? 5 + c : 5 - c;
}

// Scalar tail: binning + histogram add (one pack lane). ti in [0,10] already.
__device__ __forceinline__ void epilogue(float af, float pf, int ti, int i, int j,
                                         int* __restrict__ hist) {
    int ai = min((int)af, NB - 1);
    int pb = min((int)pf, NB - 1);
    int idx = (ai * NB + pb) * NB + ti;
    if (idx < 0) idx += NBINS;               // JAX: single negative wrap
    if ((unsigned)idx < (unsigned)NBINS && j != i)
        atomicAdd(&hist[idx], 1);
}

// Launch 1: zero the output (it is poisoned 0xAA before timing).
__global__ void fpfh_zero_out_kernel(float* __restrict__ out) {
    int t = blockIdx.x * blockDim.x + threadIdx.x;
    if (t < BNUM * NBINS) out[t] = 0.0f;
}

// Launch 2: accumulate; flush block-private histogram straight into out.
__global__ __launch_bounds__(THREADS, 4) void fpfh_accum_kernel(const float* __restrict__ x,
                                                                float* __restrict__ out) {
    __shared__ int s_hist[NBINS];

    const int b  = blockIdx.y;
    const int i0 = blockIdx.x * IPB;

    for (int t = threadIdx.x; t < NBINS; t += THREADS) s_hist[t] = 0;

    const float* __restrict__ base = x + (size_t)b * PNUM * 6;

    // i-point constants per unit u: lanes (i0+2u, i0+2u+1)
    u64f2 NPX[2], NPY[2], NPZ[2];      // -pos_i
    u64f2 NX[2],  NY[2],  NZ[2];       //  ni
    #pragma unroll
    for (int u = 0; u < 2; u++) {
        const float* p0 = base + (size_t)(i0 + 2 * u) * 6;
        const float* p1 = base + (size_t)(i0 + 2 * u + 1) * 6;
        NPX[u] = pk2(-__ldg(p0 + 0), -__ldg(p1 + 0));
        NPY[u] = pk2(-__ldg(p0 + 1), -__ldg(p1 + 1));
        NPZ[u] = pk2(-__ldg(p0 + 2), -__ldg(p1 + 2));
        NX[u]  = pk2( __ldg(p0 + 3),  __ldg(p1 + 3));
        NY[u]  = pk2( __ldg(p0 + 4),  __ldg(p1 + 4));
        NZ[u]  = pk2( __ldg(p0 + 5),  __ldg(p1 + 5));
    }
    __syncthreads();

    // theta sector constants: K_m = cot^2((2m+1)*pi/11)
    const u64f2 KB1 = pk2(11.598704f,  11.598704f);   // cot^2(pi/11)
    const u64f2 KB2 = pk2(0.7508310f,  0.7508310f);   // cot^2(3pi/11)
    const u64f2 KB3 = pk2(0.02067215f, 0.02067215f);  // cot^2(5pi/11)
    const u64f2 KB4 = pk2(0.20856093f, 0.20856093f);  // cot^2(7pi/11)
    const u64f2 KB5 = pk2(2.4212315f,  2.4212315f);   // cot^2(9pi/11)
    const u64f2 K55 = pk2(5.5f, 5.5f);

    #pragma unroll 1
    for (int jj = 0; jj < JSTEPS; jj++) {
        const int j = threadIdx.x + jj * THREADS;
        const float2* __restrict__ pj = (const float2*)(base + (size_t)j * 6);
        const float2 q0 = __ldg(pj + 0);
        const float2 q1 = __ldg(pj + 1);
        const float2 q2 = __ldg(pj + 2);
        const u64f2 JX  = pk2(q0.x, q0.x), JY  = pk2(q0.y, q0.y), JZ  = pk2(q1.x, q1.x);
        const u64f2 JNX = pk2(q1.y, q1.y), JNY = pk2(q2.x, q2.x), JNZ = pk2(q2.y, q2.y);

        #pragma unroll
        for (int u = 0; u < 2; u++) {
            // delta = pos_j - pos_i
            const u64f2 dx = f2add(JX, NPX[u]);
            const u64f2 dy = f2add(JY, NPY[u]);
            const u64f2 dz = f2add(JZ, NPZ[u]);

            const u64f2 d2   = f2fma(dx, dx, f2fma(dy, dy, f2mul(dz, dz)));
            const u64f2 pdot = f2fma(NX[u], dx, f2fma(NY[u], dy, f2mul(NZ[u], dz)));
            const u64f2 phi2 = f2mul(pdot, rsq2(d2));

            // v = cross(delta, ni)
            const u64f2 vx = f2cr(dy, NZ[u], dz, NY[u]);
            const u64f2 vy = f2cr(dz, NX[u], dx, NZ[u]);
            const u64f2 vz = f2cr(dx, NY[u], dy, NX[u]);
            const u64f2 v2 = f2fma(vx, vx, f2fma(vy, vy, f2mul(vz, vz)));
            const u64f2 adot = f2fma(vx, JNX, f2fma(vy, JNY, f2mul(vz, JNZ)));
            const u64f2 alpha2 = f2mul(adot, rsq2(v2));

            // w = cross(ni, v)
            const u64f2 wx = f2cr(NY[u], vz, NZ[u], vy);
            const u64f2 wy = f2cr(NZ[u], vx, NX[u], vz);
            const u64f2 wz = f2cr(NX[u], vy, NY[u], vx);
            const u64f2 w2   = f2fma(wx, wx, f2fma(wy, wy, f2mul(wz, wz)));
            const u64f2 wdot = f2fma(wx, JNX, f2fma(wy, JNY, f2mul(wz, JNZ)));
            const u64f2 ndot = f2fma(NX[u], JNX, f2fma(NY[u], JNY, f2mul(NZ[u], JNZ)));

            // theta sector: point (X,Y) = (ndot*|w|, wdot); A = X^2 = ndot^2*w2, B = Y^2.
            const u64f2 A   = f2mul(f2mul(ndot, ndot), w2);
            const u64f2 Bq  = f2mul(wdot, wdot);
            const u64f2 K1B = f2mul(KB1, Bq);
            const u64f2 K2B = f2mul(KB2, Bq);
            const u64f2 K3B = f2mul(KB3, Bq);
            const u64f2 K4B = f2mul(KB4, Bq);
            const u64f2 K5B = f2mul(KB5, Bq);

            float Aa, Ab;   up2(A,   Aa, Ab);
            float na, nb;   up2(ndot, na, nb);
            float ya, yb;   up2(wdot, ya, yb);
            float k1a, k1b; up2(K1B, k1a, k1b);
            float k2a, k2b; up2(K2B, k2a, k2b);
            float k3a, k3b; up2(K3B, k3a, k3b);
            float k4a, k4b; up2(K4B, k4a, k4b);
            float k5a, k5b; up2(K5B, k5a, k5b);

            const int tia = theta_bin(Aa, na, ya, k1a, k2a, k3a, k4a, k5a);
            const int tib = theta_bin(Ab, nb, yb, k1b, k2b, k3b, k4b, k5b);

            const u64f2 AF = f2fma(alpha2, K55, K55);
            const u64f2 PF = f2fma(phi2,  K55, K55);
            float afa, afb; up2(AF, afa, afb);
            float pfa, pfb; up2(PF, pfa, pfb);

            epilogue(afa, pfa, tia, i0 + 2 * u,     j, s_hist);
            epilogue(afb, pfb, tib, i0 + 2 * u + 1, j, s_hist);
        }
    }
    __syncthreads();

    // Flush directly into out: c / (1024*1023) as scaled float RED.
    const float kInv = 1.0f / 1047552.0f;
    float* __restrict__ ob = out + b * NBINS;
    for (int t = threadIdx.x; t < NBINS; t += THREADS) {
        int c = s_hist[t];
        if (c) atomicAdd(&ob[t], (float)c * kInv);
    }
}

extern "C" void kernel_launch(void* const* d_in, const int* in_sizes, int n_in,
                              void* d_out, int out_size) {
    const float* x = (const float*)d_in[0];
    float* out = (float*)d_out;

    int total = BNUM * NBINS;
    fpfh_zero_out_kernel<<<(total + 255) / 256, 256>>>(out);

    dim3 grid(BPB, BNUM);   // 256 x 8 = 2048 blocks
    fpfh_accum_kernel<<<grid, THREADS>>>(x, out);
}

// round 17
// speedup vs baseline: 1.6247x; 1.0608x over previous
#include <cuda_runtime.h>

#define PNUM    1024
#define BNUM    8
#define NB      11
#define NBINS   1331
#define IPB     4              // i-rows per block = 2 packed f32x2 units
#define THREADS 256
#define JSTEPS  (PNUM/THREADS) // 4
#define BPB     (PNUM/IPB)     // 256 blocks per batch

typedef unsigned long long u64f2;   // two packed fp32

// ---- packed f32x2 primitives (sm_100+) ----
__device__ __forceinline__ u64f2 pk2(float lo, float hi) {
    u64f2 r; asm("mov.b64 %0, {%1, %2};" : "=l"(r) : "f"(lo), "f"(hi)); return r;
}
__device__ __forceinline__ void up2(u64f2 v, float& lo, float& hi) {
    asm("mov.b64 {%0, %1}, %2;" : "=f"(lo), "=f"(hi) : "l"(v));
}
__device__ __forceinline__ u64f2 f2fma(u64f2 a, u64f2 b, u64f2 c) {
    u64f2 d; asm("fma.rn.f32x2 %0, %1, %2, %3;" : "=l"(d) : "l"(a), "l"(b), "l"(c)); return d;
}
__device__ __forceinline__ u64f2 f2mul(u64f2 a, u64f2 b) {
    u64f2 d; asm("mul.rn.f32x2 %0, %1, %2;" : "=l"(d) : "l"(a), "l"(b)); return d;
}
__device__ __forceinline__ u64f2 f2add(u64f2 a, u64f2 b) {
    u64f2 d; asm("add.rn.f32x2 %0, %1, %2;" : "=l"(d) : "l"(a), "l"(b)); return d;
}
__device__ __forceinline__ u64f2 f2sub(u64f2 a, u64f2 b) {
    u64f2 d; asm("sub.rn.f32x2 %0, %1, %2;" : "=l"(d) : "l"(a), "l"(b)); return d;
}
__device__ __forceinline__ u64f2 rsq2(u64f2 v) {   // per-lane rsqrt (MUFU is scalar)
    float a, b; up2(v, a, b);
    return pk2(rsqrtf(a), rsqrtf(b));
}
// packed cross component: a*b - c*d
__device__ __forceinline__ u64f2 f2cr(u64f2 a, u64f2 b, u64f2 c, u64f2 d) {
    return f2sub(f2mul(a, b), f2mul(c, d));
}
__device__ __forceinline__ unsigned lo32(u64f2 v) { return (unsigned)v; }
__device__ __forceinline__ unsigned hi32(u64f2 v) { return (unsigned)(v >> 32); }

// theta sector from sign bits of D_m = K_m*B - A, ndot, wdot (one lane's words).
// cpos = 3 - (s1+s2+s3); cneg = 3 + s4+s5; c = snd ? cneg : cpos; ti = sy ? 5-c : 5+c.
__device__ __forceinline__ int theta_bin_bits(unsigned d1, unsigned d2, unsigned d3,
                                              unsigned d4, unsigned d5,
                                              unsigned nd, unsigned yw) {
    const int s1 = d1 >> 31, s2 = d2 >> 31, s3 = d3 >> 31;
    const int s4 = d4 >> 31, s5 = d5 >> 31;
    const int snd = nd >> 31, sy = yw >> 31;
    const int s123 = s1 + s2 + s3;
    const int sum5 = s123 + s4 + s5;
    const int c = 3 - s123 + snd * sum5;
    return 5 + c - 2 * sy * c;
}

// Scalar tail: binning + histogram add (ti in [0,10] exact; diagonal excluded).
__device__ __forceinline__ void epilogue(float af, float pf, int ti, int i, int j,
                                         int* __restrict__ hist) {
    int ai = min((int)af, NB - 1);
    int pb = min((int)pf, NB - 1);
    int idx = ai * 121 + pb * 11 + ti;
    if (idx < 0) idx += NBINS;               // JAX: single negative wrap
    if ((unsigned)idx < (unsigned)NBINS && j != i)
        atomicAdd(&hist[idx], 1);
}

// Launch 1: zero the output (it is poisoned 0xAA before timing).
__global__ void fpfh_zero_out_kernel(float* __restrict__ out) {
    int t = blockIdx.x * blockDim.x + threadIdx.x;
    if (t < BNUM * NBINS) out[t] = 0.0f;
}

// Launch 2: accumulate; flush block-private histogram straight into out.
__global__ __launch_bounds__(THREADS, 4) void fpfh_accum_kernel(const float* __restrict__ x,
                                                                float* __restrict__ out) {
    __shared__ int s_hist[NBINS];

    const int b  = blockIdx.y;
    const int i0 = blockIdx.x * IPB;

    for (int t = threadIdx.x; t < NBINS; t += THREADS) s_hist[t] = 0;

    const float* __restrict__ base = x + (size_t)b * PNUM * 6;

    // i-point constants per unit u: lanes (i0+2u, i0+2u+1)
    u64f2 NPX[2], NPY[2], NPZ[2];      // -pos_i
    u64f2 NX[2],  NY[2],  NZ[2];       //  ni
    #pragma unroll
    for (int u = 0; u < 2; u++) {
        const float* p0 = base + (size_t)(i0 + 2 * u) * 6;
        const float* p1 = base + (size_t)(i0 + 2 * u + 1) * 6;
        NPX[u] = pk2(-__ldg(p0 + 0), -__ldg(p1 + 0));
        NPY[u] = pk2(-__ldg(p0 + 1), -__ldg(p1 + 1));
        NPZ[u] = pk2(-__ldg(p0 + 2), -__ldg(p1 + 2));
        NX[u]  = pk2( __ldg(p0 + 3),  __ldg(p1 + 3));
        NY[u]  = pk2( __ldg(p0 + 4),  __ldg(p1 + 4));
        NZ[u]  = pk2( __ldg(p0 + 5),  __ldg(p1 + 5));
    }
    __syncthreads();

    // theta sector constants: K_m = cot^2((2m+1)*pi/11)
    const u64f2 KB1 = pk2(11.598704f,  11.598704f);   // cot^2(pi/11)
    const u64f2 KB2 = pk2(0.7508310f,  0.7508310f);   // cot^2(3pi/11)
    const u64f2 KB3 = pk2(0.02067215f, 0.02067215f);  // cot^2(5pi/11)
    const u64f2 KB4 = pk2(0.20856093f, 0.20856093f);  // cot^2(7pi/11)
    const u64f2 KB5 = pk2(2.4212315f,  2.4212315f);   // cot^2(9pi/11)
    const u64f2 K55 = pk2(5.5f, 5.5f);
    const u64f2 ZERO2 = pk2(0.0f, 0.0f);

    #pragma unroll 1
    for (int jj = 0; jj < JSTEPS; jj++) {
        const int j = threadIdx.x + jj * THREADS;
        const float2* __restrict__ pj = (const float2*)(base + (size_t)j * 6);
        const float2 q0 = __ldg(pj + 0);
        const float2 q1 = __ldg(pj + 1);
        const float2 q2 = __ldg(pj + 2);
        const u64f2 JX  = pk2(q0.x, q0.x), JY  = pk2(q0.y, q0.y), JZ  = pk2(q1.x, q1.x);
        const u64f2 JNX = pk2(q1.y, q1.y), JNY = pk2(q2.x, q2.x), JNZ = pk2(q2.y, q2.y);

        #pragma unroll
        for (int u = 0; u < 2; u++) {
            // delta = pos_j - pos_i
            const u64f2 dx = f2add(JX, NPX[u]);
            const u64f2 dy = f2add(JY, NPY[u]);
            const u64f2 dz = f2add(JZ, NPZ[u]);

            const u64f2 d2   = f2fma(dx, dx, f2fma(dy, dy, f2mul(dz, dz)));
            const u64f2 pdot = f2fma(NX[u], dx, f2fma(NY[u], dy, f2mul(NZ[u], dz)));
            const u64f2 phi2 = f2mul(pdot, rsq2(d2));

            // v = cross(delta, ni)
            const u64f2 vx = f2cr(dy, NZ[u], dz, NY[u]);
            const u64f2 vy = f2cr(dz, NX[u], dx, NZ[u]);
            const u64f2 vz = f2cr(dx, NY[u], dy, NX[u]);
            const u64f2 v2 = f2fma(vx, vx, f2fma(vy, vy, f2mul(vz, vz)));
            const u64f2 adot = f2fma(vx, JNX, f2fma(vy, JNY, f2mul(vz, JNZ)));
            const u64f2 alpha2 = f2mul(adot, rsq2(v2));

            // w = cross(ni, v)
            const u64f2 wx = f2cr(NY[u], vz, NZ[u], vy);
            const u64f2 wy = f2cr(NZ[u], vx, NX[u], vz);
            const u64f2 wz = f2cr(NX[u], vy, NY[u], vx);
            const u64f2 w2   = f2fma(wx, wx, f2fma(wy, wy, f2mul(wz, wz)));
            const u64f2 wdot = f2fma(wx, JNX, f2fma(wy, JNY, f2mul(wz, JNZ)));
            const u64f2 ndot = f2fma(NX[u], JNX, f2fma(NY[u], JNY, f2mul(NZ[u], JNZ)));

            // theta sector via sign bits: A = ndot^2*w2, B = wdot^2, D_m = K_m*B - A.
            const u64f2 A  = f2mul(f2mul(ndot, ndot), w2);
            const u64f2 Bq = f2mul(wdot, wdot);
            const u64f2 nA = f2sub(ZERO2, A);
            const u64f2 D1 = f2fma(KB1, Bq, nA);
            const u64f2 D2 = f2fma(KB2, Bq, nA);
            const u64f2 D3 = f2fma(KB3, Bq, nA);
            const u64f2 D4 = f2fma(KB4, Bq, nA);
            const u64f2 D5 = f2fma(KB5, Bq, nA);

            const int tia = theta_bin_bits(lo32(D1), lo32(D2), lo32(D3),
                                           lo32(D4), lo32(D5), lo32(ndot), lo32(wdot));
            const int tib = theta_bin_bits(hi32(D1), hi32(D2), hi32(D3),
                                           hi32(D4), hi32(D5), hi32(ndot), hi32(wdot));

            const u64f2 AF = f2fma(alpha2, K55, K55);
            const u64f2 PF = f2fma(phi2,  K55, K55);
            float afa, afb; up2(AF, afa, afb);
            float pfa, pfb; up2(PF, pfa, pfb);

            epilogue(afa, pfa, tia, i0 + 2 * u,     j, s_hist);
            epilogue(afb, pfb, tib, i0 + 2 * u + 1, j, s_hist);
        }
    }
    __syncthreads();

    // Flush directly into out: c / (1024*1023) as scaled float RED.
    const float kInv = 1.0f / 1047552.0f;
    float* __restrict__ ob = out + b * NBINS;
    for (int t = threadIdx.x; t < NBINS; t += THREADS) {
        int c = s_hist[t];
        if (c) atomicAdd(&ob[t], (float)c * kInv);
    }
}

extern "C" void kernel_launch(void* const* d_in, const int* in_sizes, int n_in,
                              void* d_out, int out_size) {
    const float* x = (const float*)d_in[0];
    float* out = (float*)d_out;

    int total = BNUM * NBINS;
    fpfh_zero_out_kernel<<<(total + 255) / 256, 256>>>(out);

    dim3 grid(BPB, BNUM);   // 256 x 8 = 2048 blocks
    fpfh_accum_kernel<<<grid, THREADS>>>(x, out);
}